// round 14
// baseline (speedup 1.0000x reference)
#include <cuda_runtime.h>
#include <cstdint>

// ---------------- problem constants ----------------
#define ROWG   64
#define IN_DIM 1024
#define OUT_D  1024
#define BATCH  512

// ---------------- tiling ----------------
#define BM 128
#define BN 128
#define BK 64
#define KT (IN_DIM / BK)   // 16 k-tiles

// ---------------- smem layout (bytes) ----------------
#define A_ROW_B 128                 // 64 fp16 = 8 chunks, rotated-XOR swizzle
#define A_STG   (BM * A_ROW_B)      // 16384
#define B_ROW_B 272                 // 128 fp16 (256B) + 16B pad
#define B_STG   (BK * B_ROW_B)      // 17408
#define STAGES  3
#define SMEM_TOTAL (STAGES * (A_STG + B_STG))  // 101376 per CTA -> 2 CTAs/SM

__device__ __forceinline__ uint32_t packh(float hi, float lo) {
    uint32_t w;
    asm("cvt.rn.f16x2.f32 %0, %1, %2;" : "=r"(w) : "f"(hi), "f"(lo));
    return w;
}

// rotated swizzle: bijective on 0..7, adjacent rows -> opposite 4-chunk halves
__device__ __forceinline__ int swz(int row) {
    return ((row & 1) << 2) | ((row & 6) >> 1);
}

#define LDSM4(R, ADDR) \
    asm volatile("ldmatrix.sync.aligned.m8n8.x4.shared.b16 {%0,%1,%2,%3}, [%4];" \
        : "=r"((R)[0]), "=r"((R)[1]), "=r"((R)[2]), "=r"((R)[3]) : "r"(ADDR))

#define LDSM4T(R, ADDR) \
    asm volatile("ldmatrix.sync.aligned.m8n8.x4.trans.shared.b16 {%0,%1,%2,%3}, [%4];" \
        : "=r"((R)[0]), "=r"((R)[1]), "=r"((R)[2]), "=r"((R)[3]) : "r"(ADDR))

#define MMA16(C, A, B0, B1) \
    asm volatile("mma.sync.aligned.m16n8k16.row.col.f32.f16.f16.f32 " \
        "{%0,%1,%2,%3}, {%4,%5,%6,%7}, {%8,%9}, {%0,%1,%2,%3};" \
        : "+f"((C)[0]), "+f"((C)[1]), "+f"((C)[2]), "+f"((C)[3]) \
        : "r"((A)[0]), "r"((A)[1]), "r"((A)[2]), "r"((A)[3]), "r"(B0), "r"(B1))

__global__ __launch_bounds__(128, 2)
void gmlp_f16c2(const float* __restrict__ x,
                const float* __restrict__ W,
                const float* __restrict__ bias,
                float* __restrict__ out)
{
    extern __shared__ __align__(16) char smem[];
    const uint32_t sbA = (uint32_t)__cvta_generic_to_shared(smem);
    const uint32_t sbB = sbA + STAGES * A_STG;

    const int r  = blockIdx.z;
    const int n0 = blockIdx.x * BN;
    const int m0 = blockIdx.y * BM;

    const int tid  = threadIdx.x;
    const int wid  = tid >> 5;
    const int lane = tid & 31;
    const int wm   = wid & 1;            // 2 m-warps of 64 rows
    const int wn   = wid >> 1;           // 2 n-warps of 64 cols
    const int g    = lane >> 2;
    const int tg   = lane & 3;

    // ---- loader: A — 4 thr/row, 32 rows/pass, 4 passes ----
    const int arow = tid >> 2;           // 0..31
    const float* xA = x + (size_t)(m0 + arow) * (ROWG * IN_DIM)
                        + (size_t)r * IN_DIM + (tid & 3) * 8;
    const size_t A_P = (size_t)32 * (ROWG * IN_DIM);     // +32 batch rows
    const int e_ar = swz(arow);
    const uint32_t saA0 = sbA + arow * A_ROW_B + ((((tid & 3)    ) ^ e_ar) * 16);
    const uint32_t saA1 = sbA + arow * A_ROW_B + ((((tid & 3) | 4) ^ e_ar) * 16);

    // ---- loader: B — 16 thr/row, 8 rows/pass, 4 passes per k32-half ----
    const int brow = tid >> 4;           // 0..7
    const float* xB = W + (size_t)r * IN_DIM * OUT_D
                        + (size_t)brow * OUT_D + n0 + (tid & 15) * 8;
    const uint32_t saB = sbB + brow * B_ROW_B + (tid & 15) * 16;

    // ---- consumer ldmatrix base addresses ----
    const int hb = lane >> 4;
    const int e_ln = swz(lane & 7);
    const uint32_t aBase = sbA + (wm * 64 + (lane & 15)) * A_ROW_B;
    uint32_t aoff[4];
    #pragma unroll
    for (int ks = 0; ks < 4; ks++)
        aoff[ks] = (uint32_t)(((2 * ks + hb) ^ e_ln) * 16);
    const uint32_t bBase = sbB + ((lane & 7) + ((lane >> 3) & 1) * 8) * B_ROW_B
                               + (wn * 8 + hb) * 16;

    float acc[4][8][4];
    #pragma unroll
    for (int mt = 0; mt < 4; mt++)
        #pragma unroll
        for (int nt = 0; nt < 8; nt++)
            #pragma unroll
            for (int i = 0; i < 4; i++)
                acc[mt][nt][i] = 0.0f;

    float st[32];   // single staging buffer, cycled A/B/A/B

// A half H of tile T -> st
#define LOAD_A(T, H) do {                                                    \
    _Pragma("unroll")                                                        \
    for (int p_ = 0; p_ < 4; p_++) {                                         \
        const float4* a_ = (const float4*)(xA + (size_t)((T) * BK + (H) * 32) + p_ * A_P); \
        float4 v0_ = a_[0], v1_ = a_[1];                                     \
        st[p_*8+0]=v0_.x; st[p_*8+1]=v0_.y; st[p_*8+2]=v0_.z; st[p_*8+3]=v0_.w; \
        st[p_*8+4]=v1_.x; st[p_*8+5]=v1_.y; st[p_*8+6]=v1_.z; st[p_*8+7]=v1_.w; \
    }                                                                        \
} while (0)

#define STS_A(BUF, H) do {                                                   \
    const uint32_t sa_ = ((H) ? saA1 : saA0) + (BUF) * A_STG;                \
    _Pragma("unroll")                                                        \
    for (int p_ = 0; p_ < 4; p_++) {                                         \
        asm volatile("st.shared.v4.b32 [%0], {%1,%2,%3,%4};"                 \
            :: "r"(sa_ + p_ * (32 * A_ROW_B)),                               \
               "r"(packh(st[p_*8+1],st[p_*8+0])), "r"(packh(st[p_*8+3],st[p_*8+2])), \
               "r"(packh(st[p_*8+5],st[p_*8+4])), "r"(packh(st[p_*8+7],st[p_*8+6]))); \
    }                                                                        \
} while (0)

// B half H (k32) of tile T -> st
#define LOAD_B(T, H) do {                                                    \
    _Pragma("unroll")                                                        \
    for (int p_ = 0; p_ < 4; p_++) {                                         \
        const float4* b_ = (const float4*)(xB + (size_t)((T) * BK + (H) * 32 + p_ * 8) * OUT_D); \
        float4 v0_ = b_[0], v1_ = b_[1];                                     \
        st[p_*8+0]=v0_.x; st[p_*8+1]=v0_.y; st[p_*8+2]=v0_.z; st[p_*8+3]=v0_.w; \
        st[p_*8+4]=v1_.x; st[p_*8+5]=v1_.y; st[p_*8+6]=v1_.z; st[p_*8+7]=v1_.w; \
    }                                                                        \
} while (0)

#define STS_B(BUF, H) do {                                                   \
    const uint32_t sb_ = saB + (BUF) * B_STG + (H) * (32 * B_ROW_B);         \
    _Pragma("unroll")                                                        \
    for (int p_ = 0; p_ < 4; p_++) {                                         \
        asm volatile("st.shared.v4.b32 [%0], {%1,%2,%3,%4};"                 \
            :: "r"(sb_ + p_ * (8 * B_ROW_B)),                                \
               "r"(packh(st[p_*8+1],st[p_*8+0])), "r"(packh(st[p_*8+3],st[p_*8+2])), \
               "r"(packh(st[p_*8+5],st[p_*8+4])), "r"(packh(st[p_*8+7],st[p_*8+6]))); \
    }                                                                        \
} while (0)

// one k16 group of stage BUF
#define COMPUTE_KS(BUF, KS) do {                                             \
    uint32_t a_[4][4];                                                       \
    _Pragma("unroll")                                                        \
    for (int mt_ = 0; mt_ < 4; mt_++)                                        \
        LDSM4(a_[mt_], aBase + (BUF) * A_STG + mt_ * (16 * A_ROW_B) + aoff[KS]); \
    _Pragma("unroll")                                                        \
    for (int p_ = 0; p_ < 4; p_++) {                                         \
        uint32_t bb_[4];                                                     \
        LDSM4T(bb_, bBase + (BUF) * B_STG + (KS) * (16 * B_ROW_B) + p_ * 32); \
        _Pragma("unroll")                                                    \
        for (int mt_ = 0; mt_ < 4; mt_++) {                                  \
            MMA16(acc[mt_][2 * p_],     a_[mt_], bb_[0], bb_[1]);            \
            MMA16(acc[mt_][2 * p_ + 1], a_[mt_], bb_[2], bb_[3]);            \
        }                                                                    \
    }                                                                        \
} while (0)

    // ---- prologue: tile0 fully staged; A-half0 of tile1 in regs ----
    LOAD_A(0, 0);  STS_A(0, 0);
    LOAD_B(0, 0);  STS_B(0, 0);
    LOAD_A(0, 1);  STS_A(0, 1);
    LOAD_B(0, 1);  STS_B(0, 1);
    LOAD_A(1, 0);
    __syncthreads();

    // ---- main loop: 3-stage ring, quarter-phase staging ----
    #pragma unroll 1
    for (int kt = 0; kt < KT; kt++) {
        const int s_cmp = kt % STAGES;
        const int s_nxt = (kt + 1) % STAGES;
        if (kt + 1 < KT) { STS_A(s_nxt, 0); LOAD_B(kt + 1, 0); }
        COMPUTE_KS(s_cmp, 0);
        if (kt + 1 < KT) { STS_B(s_nxt, 0); LOAD_A(kt + 1, 1); }
        COMPUTE_KS(s_cmp, 1);
        if (kt + 1 < KT) { STS_A(s_nxt, 1); LOAD_B(kt + 1, 1); }
        COMPUTE_KS(s_cmp, 2);
        if (kt + 1 < KT) { STS_B(s_nxt, 1); }
        if (kt + 2 < KT) { LOAD_A(kt + 2, 0); }
        COMPUTE_KS(s_cmp, 3);
        __syncthreads();
    }

    // ---- epilogue: add bias, store ----
    const float* bp = bias + (size_t)r * OUT_D + n0;
    #pragma unroll
    for (int mt = 0; mt < 4; mt++) {
        #pragma unroll
        for (int nt = 0; nt < 8; nt++) {
            int row0 = wm * 64 + mt * 16 + g;
            int col  = wn * 64 + nt * 8 + tg * 2;
            float b0 = bp[col];
            float b1 = bp[col + 1];
            float2 v0 = make_float2(acc[mt][nt][0] + b0, acc[mt][nt][1] + b1);
            float2 v1 = make_float2(acc[mt][nt][2] + b0, acc[mt][nt][3] + b1);
            size_t o0 = ((size_t)(m0 + row0)     * ROWG + r) * OUT_D + n0 + col;
            size_t o1 = ((size_t)(m0 + row0 + 8) * ROWG + r) * OUT_D + n0 + col;
            *reinterpret_cast<float2*>(out + o0) = v0;
            *reinterpret_cast<float2*>(out + o1) = v1;
        }
    }
}

extern "C" void kernel_launch(void* const* d_in, const int* in_sizes, int n_in,
                              void* d_out, int out_size) {
    const float* x    = (const float*)d_in[0];  // (512, 64, 1024)
    const float* W    = (const float*)d_in[1];  // (64, 1024, 1024)
    const float* bias = (const float*)d_in[2];  // (64, 1024)
    float* out = (float*)d_out;                 // (512, 64, 1024)

    cudaFuncSetAttribute(gmlp_f16c2,
                         cudaFuncAttributeMaxDynamicSharedMemorySize, SMEM_TOTAL);
    dim3 grid(OUT_D / BN, BATCH / BM, ROWG);    // (8, 4, 64)
    gmlp_f16c2<<<grid, 128, SMEM_TOTAL>>>(x, W, bias, out);
}

// round 15
// speedup vs baseline: 1.0421x; 1.0421x over previous
#include <cuda_runtime.h>
#include <cstdint>

// ---------------- problem constants ----------------
#define ROWG   64
#define IN_DIM 1024
#define OUT_D  1024
#define BATCH  512

// ---------------- tiling ----------------
#define BM 128
#define BN 256
#define BK 64
#define KT (IN_DIM / BK)   // 16 k-tiles

// ---------------- smem layout (bytes) ----------------
#define A_ROW_B 128                 // 64 fp16 = 8 chunks, rotated-XOR swizzle
#define A_STG   (BM * A_ROW_B)      // 16384
#define B_ROW_B 528                 // 256 fp16 (512B) + 16B pad
#define B_STG   (BK * B_ROW_B)      // 33792
#define STAGES  3
#define SMEM_TOTAL (STAGES * (A_STG + B_STG))  // 150528

__device__ __forceinline__ uint32_t packh(float hi, float lo) {
    uint32_t w;
    asm("cvt.rn.f16x2.f32 %0, %1, %2;" : "=r"(w) : "f"(hi), "f"(lo));
    return w;
}

// rotated swizzle: bijective on 0..7, adjacent rows -> opposite 4-chunk halves
__device__ __forceinline__ int swz(int row) {
    return ((row & 1) << 2) | ((row & 6) >> 1);
}

#define LDSM4(R, ADDR) \
    asm volatile("ldmatrix.sync.aligned.m8n8.x4.shared.b16 {%0,%1,%2,%3}, [%4];" \
        : "=r"((R)[0]), "=r"((R)[1]), "=r"((R)[2]), "=r"((R)[3]) : "r"(ADDR))

#define LDSM4T(R, ADDR) \
    asm volatile("ldmatrix.sync.aligned.m8n8.x4.trans.shared.b16 {%0,%1,%2,%3}, [%4];" \
        : "=r"((R)[0]), "=r"((R)[1]), "=r"((R)[2]), "=r"((R)[3]) : "r"(ADDR))

#define MMA16(C, A, B0, B1) \
    asm volatile("mma.sync.aligned.m16n8k16.row.col.f32.f16.f16.f32 " \
        "{%0,%1,%2,%3}, {%4,%5,%6,%7}, {%8,%9}, {%0,%1,%2,%3};" \
        : "+f"((C)[0]), "+f"((C)[1]), "+f"((C)[2]), "+f"((C)[3]) \
        : "r"((A)[0]), "r"((A)[1]), "r"((A)[2]), "r"((A)[3]), "r"(B0), "r"(B1))

__global__ __launch_bounds__(256, 1)
void gmlp_f16rot(const float* __restrict__ x,
                 const float* __restrict__ W,
                 const float* __restrict__ bias,
                 float* __restrict__ out)
{
    extern __shared__ __align__(16) char smem[];
    const uint32_t sbA = (uint32_t)__cvta_generic_to_shared(smem);
    const uint32_t sbB = sbA + STAGES * A_STG;

    const int r  = blockIdx.z;
    const int n0 = blockIdx.x * BN;
    const int m0 = blockIdx.y * BM;

    const int tid  = threadIdx.x;
    const int wid  = tid >> 5;
    const int lane = tid & 31;
    const int wm   = wid & 1;            // 2 m-warps of 64 rows
    const int wn   = wid >> 1;           // 4 n-warps of 64 cols
    const int g    = lane >> 2;
    const int tg   = lane & 3;
    const int rot  = wid & 3;            // per-warp k-group rotation

    // ---- loader: A — 4 threads per 32-col half-row, fully coalesced ----
    const int arow = tid >> 2;           // rows 0..63 (c0), +64 (c1)
    const float* xA = x + (size_t)(m0 + arow) * (ROWG * IN_DIM)
                        + (size_t)r * IN_DIM + (tid & 3) * 8;
    const size_t A_C1 = (size_t)64 * (ROWG * IN_DIM);
    const int e_ar = swz(arow);
    const uint32_t saA0 = sbA + arow * A_ROW_B + ((((tid & 3)    ) ^ e_ar) * 16);
    const uint32_t saA1 = sbA + arow * A_ROW_B + ((((tid & 3) + 4) ^ e_ar) * 16);

    // ---- loader: B — 8 threads per 256-col row (4 segs), fully coalesced ----
    const int brow = tid >> 3;           // k-rows 0..31 within half
    const float* xB = W + (size_t)r * IN_DIM * OUT_D
                        + (size_t)brow * OUT_D + n0 + (tid & 7) * 8;
    const uint32_t saB = sbB + brow * B_ROW_B + (tid & 7) * 16;

    // ---- consumer ldmatrix base addresses ----
    const int hb = lane >> 4;                       // chunk half bit
    const int e_ln = swz(lane & 7);
    const uint32_t aBase = sbA + (wm * 64 + (lane & 15)) * A_ROW_B;
    uint32_t aoff[4];
    #pragma unroll
    for (int ks = 0; ks < 4; ks++)
        aoff[ks] = (uint32_t)(((2 * ks + hb) ^ e_ln) * 16);
    const uint32_t bBase = sbB + ((lane & 7) + ((lane >> 3) & 1) * 8) * B_ROW_B
                               + (wn * 8 + hb) * 16;

    float acc[4][8][4];
    #pragma unroll
    for (int mt = 0; mt < 4; mt++)
        #pragma unroll
        for (int nt = 0; nt < 8; nt++)
            #pragma unroll
            for (int i = 0; i < 4; i++)
                acc[mt][nt][i] = 0.0f;

    float stA[16], stB[32];

// load half H (32 k-cols) of tile T into staging regs
#define LOAD_H(T, H) do {                                                    \
    const float4* a0_ = (const float4*)(xA + (size_t)(T) * BK + (H) * 32);   \
    const float4* a1_ = (const float4*)(xA + (size_t)(T) * BK + (H) * 32 + A_C1); \
    float4 v_;                                                               \
    v_ = a0_[0]; stA[0]=v_.x; stA[1]=v_.y; stA[2]=v_.z; stA[3]=v_.w;         \
    v_ = a0_[1]; stA[4]=v_.x; stA[5]=v_.y; stA[6]=v_.z; stA[7]=v_.w;         \
    v_ = a1_[0]; stA[8]=v_.x; stA[9]=v_.y; stA[10]=v_.z; stA[11]=v_.w;       \
    v_ = a1_[1]; stA[12]=v_.x; stA[13]=v_.y; stA[14]=v_.z; stA[15]=v_.w;     \
    _Pragma("unroll")                                                        \
    for (int c_ = 0; c_ < 4; c_++) {                                         \
        const float4* b_ = (const float4*)(xB + (size_t)((T) * BK + (H) * 32) * OUT_D + c_ * 64); \
        float4 u0_ = b_[0], u1_ = b_[1];                                     \
        stB[c_*8+0]=u0_.x; stB[c_*8+1]=u0_.y; stB[c_*8+2]=u0_.z; stB[c_*8+3]=u0_.w; \
        stB[c_*8+4]=u1_.x; stB[c_*8+5]=u1_.y; stB[c_*8+6]=u1_.z; stB[c_*8+7]=u1_.w; \
    }                                                                        \
} while (0)

// store staged half H into stage BUF
#define STS_H(BUF, H) do {                                                   \
    const uint32_t sa_ = ((H) ? saA1 : saA0) + (BUF) * A_STG;                \
    asm volatile("st.shared.v4.b32 [%0], {%1,%2,%3,%4};"                     \
        :: "r"(sa_),                                                         \
           "r"(packh(stA[1],stA[0])), "r"(packh(stA[3],stA[2])),             \
           "r"(packh(stA[5],stA[4])), "r"(packh(stA[7],stA[6])));            \
    asm volatile("st.shared.v4.b32 [%0], {%1,%2,%3,%4};"                     \
        :: "r"(sa_ + 64 * A_ROW_B),                                          \
           "r"(packh(stA[9],stA[8])), "r"(packh(stA[11],stA[10])),           \
           "r"(packh(stA[13],stA[12])), "r"(packh(stA[15],stA[14])));        \
    const uint32_t sb_ = saB + (BUF) * B_STG + (H) * (32 * B_ROW_B);         \
    _Pragma("unroll")                                                        \
    for (int c_ = 0; c_ < 4; c_++) {                                         \
        asm volatile("st.shared.v4.b32 [%0], {%1,%2,%3,%4};"                 \
            :: "r"(sb_ + c_ * 128),                                          \
               "r"(packh(stB[c_*8+1],stB[c_*8+0])), "r"(packh(stB[c_*8+3],stB[c_*8+2])), \
               "r"(packh(stB[c_*8+5],stB[c_*8+4])), "r"(packh(stB[c_*8+7],stB[c_*8+6]))); \
    }                                                                        \
} while (0)

// compute one k16 group KS of stage BUF (KS is a runtime value 0..3)
#define COMPUTE_KS(BUF, KS) do {                                             \
    const int ksv_ = (KS);                                                   \
    uint32_t a_[4][4];                                                       \
    _Pragma("unroll")                                                        \
    for (int mt_ = 0; mt_ < 4; mt_++)                                        \
        LDSM4(a_[mt_], aBase + (BUF) * A_STG + mt_ * (16 * A_ROW_B) + aoff[ksv_]); \
    const uint32_t bks_ = bBase + (BUF) * B_STG + ksv_ * (16 * B_ROW_B);     \
    _Pragma("unroll")                                                        \
    for (int p_ = 0; p_ < 4; p_++) {                                         \
        uint32_t bb_[4];                                                     \
        LDSM4T(bb_, bks_ + p_ * 32);                                         \
        _Pragma("unroll")                                                    \
        for (int mt_ = 0; mt_ < 4; mt_++) {                                  \
            MMA16(acc[mt_][2 * p_],     a_[mt_], bb_[0], bb_[1]);            \
            MMA16(acc[mt_][2 * p_ + 1], a_[mt_], bb_[2], bb_[3]);            \
        }                                                                    \
    }                                                                        \
} while (0)

    // ---- prologue: tile0 fully staged; tile1 half0 in regs ----
    LOAD_H(0, 0);  STS_H(0, 0);
    LOAD_H(0, 1);  STS_H(0, 1);
    LOAD_H(1, 0);
    __syncthreads();

    // ---- main loop: 3-stage ring, rotated k-groups, deferred STS ----
    #pragma unroll 1
    for (int kt = 0; kt < KT; kt++) {
        const int s_cmp = kt % STAGES;
        const int s_nxt = (kt + 1) % STAGES;
        COMPUTE_KS(s_cmp, rot);
        if (kt + 1 < KT) { STS_H(s_nxt, 0); LOAD_H(kt + 1, 1); }
        COMPUTE_KS(s_cmp, (rot + 1) & 3);
        COMPUTE_KS(s_cmp, (rot + 2) & 3);
        if (kt + 1 < KT) { STS_H(s_nxt, 1); }
        if (kt + 2 < KT) { LOAD_H(kt + 2, 0); }
        COMPUTE_KS(s_cmp, (rot + 3) & 3);
        __syncthreads();
    }

    // ---- epilogue: add bias, store ----
    const float* bp = bias + (size_t)r * OUT_D + n0;
    #pragma unroll
    for (int mt = 0; mt < 4; mt++) {
        #pragma unroll
        for (int nt = 0; nt < 8; nt++) {
            int row0 = wm * 64 + mt * 16 + g;
            int col  = wn * 64 + nt * 8 + tg * 2;
            float b0 = bp[col];
            float b1 = bp[col + 1];
            float2 v0 = make_float2(acc[mt][nt][0] + b0, acc[mt][nt][1] + b1);
            float2 v1 = make_float2(acc[mt][nt][2] + b0, acc[mt][nt][3] + b1);
            size_t o0 = ((size_t)(m0 + row0)     * ROWG + r) * OUT_D + n0 + col;
            size_t o1 = ((size_t)(m0 + row0 + 8) * ROWG + r) * OUT_D + n0 + col;
            *reinterpret_cast<float2*>(out + o0) = v0;
            *reinterpret_cast<float2*>(out + o1) = v1;
        }
    }
}

extern "C" void kernel_launch(void* const* d_in, const int* in_sizes, int n_in,
                              void* d_out, int out_size) {
    const float* x    = (const float*)d_in[0];  // (512, 64, 1024)
    const float* W    = (const float*)d_in[1];  // (64, 1024, 1024)
    const float* bias = (const float*)d_in[2];  // (64, 1024)
    float* out = (float*)d_out;                 // (512, 64, 1024)

    cudaFuncSetAttribute(gmlp_f16rot,
                         cudaFuncAttributeMaxDynamicSharedMemorySize, SMEM_TOTAL);
    dim3 grid(OUT_D / BN, BATCH / BM, ROWG);    // (4, 4, 64)
    gmlp_f16rot<<<grid, 256, SMEM_TOTAL>>>(x, W, bias, out);
}

// round 16
// speedup vs baseline: 1.5692x; 1.5059x over previous
#include <cuda_runtime.h>
#include <cstdint>

// ---------------- problem constants ----------------
#define ROWG   64
#define IN_DIM 1024
#define OUT_D  1024
#define BATCH  512

// ---------------- tiling ----------------
#define BM 128
#define BN 256
#define BK 64
#define KT (IN_DIM / BK)   // 16 k-tiles

// ---------------- smem layout (bytes) ----------------
#define A_ROW_B 128                 // 64 fp16 = 8 chunks, rotated-XOR swizzle
#define A_STG   (BM * A_ROW_B)      // 16384
#define B_ROW_B 528                 // 256 fp16 (512B) + 16B pad
#define B_STG   (BK * B_ROW_B)      // 33792
#define STAGES  3
#define SMEM_TOTAL (STAGES * (A_STG + B_STG))  // 150528

__device__ __forceinline__ uint32_t packh(float hi, float lo) {
    uint32_t w;
    asm("cvt.rn.f16x2.f32 %0, %1, %2;" : "=r"(w) : "f"(hi), "f"(lo));
    return w;
}

// rotated swizzle: bijective on 0..7, adjacent rows -> opposite 4-chunk halves
__device__ __forceinline__ int swz(int row) {
    return ((row & 1) << 2) | ((row & 6) >> 1);
}

#define LDSM4(R, ADDR) \
    asm volatile("ldmatrix.sync.aligned.m8n8.x4.shared.b16 {%0,%1,%2,%3}, [%4];" \
        : "=r"((R)[0]), "=r"((R)[1]), "=r"((R)[2]), "=r"((R)[3]) : "r"(ADDR))

#define LDSM4T(R, ADDR) \
    asm volatile("ldmatrix.sync.aligned.m8n8.x4.trans.shared.b16 {%0,%1,%2,%3}, [%4];" \
        : "=r"((R)[0]), "=r"((R)[1]), "=r"((R)[2]), "=r"((R)[3]) : "r"(ADDR))

#define MMA16(C, A, B0, B1) \
    asm volatile("mma.sync.aligned.m16n8k16.row.col.f32.f16.f16.f32 " \
        "{%0,%1,%2,%3}, {%4,%5,%6,%7}, {%8,%9}, {%0,%1,%2,%3};" \
        : "+f"((C)[0]), "+f"((C)[1]), "+f"((C)[2]), "+f"((C)[3]) \
        : "r"((A)[0]), "r"((A)[1]), "r"((A)[2]), "r"((A)[3]), "r"(B0), "r"(B1))

__global__ __launch_bounds__(256, 1)
void gmlp_f16cw(const float* __restrict__ x,
                const float* __restrict__ W,
                const float* __restrict__ bias,
                float* __restrict__ out)
{
    extern __shared__ __align__(16) char smem[];
    const uint32_t sbA = (uint32_t)__cvta_generic_to_shared(smem);
    const uint32_t sbB = sbA + STAGES * A_STG;

    const int r  = blockIdx.z;
    const int n0 = blockIdx.x * BN;
    const int m0 = blockIdx.y * BM;

    const int tid  = threadIdx.x;
    const int wid  = tid >> 5;
    const int lane = tid & 31;
    const int wm   = wid & 1;            // 2 m-warps of 64 rows
    const int wn   = wid >> 1;           // 4 n-warps of 64 cols
    const int g    = lane >> 2;
    const int tg   = lane & 3;

    // ---- loader: A — 8 lanes per 128B fp32 half-row (full-line instrs), 4 passes ----
    const int arow = tid >> 3;            // 0..31, rows arow + 32p
    const int achk = tid & 7;             // 16B chunk within half-row
    const float* xA = x + (size_t)(m0 + arow) * (ROWG * IN_DIM)
                        + (size_t)r * IN_DIM + achk * 4;
    const size_t A_P = (size_t)32 * (ROWG * IN_DIM);     // +32 batch rows
    const int e_ar = swz(arow & 7);
    // fp16 dest: global chunk = H*4 + (achk>>1), swizzled; 8B half selected by achk&1
    const uint32_t saA0 = sbA + arow * A_ROW_B
                        + ((((achk >> 1)    ) ^ e_ar) * 16) + (achk & 1) * 8;
    const uint32_t saA1 = sbA + arow * A_ROW_B
                        + ((((achk >> 1) + 4) ^ e_ar) * 16) + (achk & 1) * 8;

    // ---- loader: B — 16 lanes per 256B segment, 2 rows per warp-instr ----
    const int bq_row = tid >> 4;          // 0..15, rows bq_row + 16*(q&1)
    const int bq_col = tid & 15;          // 16B unit within 256B segment
    const float* xB = W + (size_t)r * IN_DIM * OUT_D
                        + (size_t)bq_row * OUT_D + n0 + bq_col * 4;
    const uint32_t saB = sbB + bq_row * B_ROW_B + bq_col * 8;

    // ---- consumer ldmatrix base addresses (identical to R13) ----
    const int hb = lane >> 4;
    const int e_ln = swz(lane & 7);
    const uint32_t aBase = sbA + (wm * 64 + (lane & 15)) * A_ROW_B;
    uint32_t aoff[4];
    #pragma unroll
    for (int ks = 0; ks < 4; ks++)
        aoff[ks] = (uint32_t)(((2 * ks + hb) ^ e_ln) * 16);
    const uint32_t bBase = sbB + ((lane & 7) + ((lane >> 3) & 1) * 8) * B_ROW_B
                               + (wn * 8 + hb) * 16;

    float acc[4][8][4];
    #pragma unroll
    for (int mt = 0; mt < 4; mt++)
        #pragma unroll
        for (int nt = 0; nt < 8; nt++)
            #pragma unroll
            for (int i = 0; i < 4; i++)
                acc[mt][nt][i] = 0.0f;

    float stA[16], stB[32];

// load half H (32 k-cols) of tile T into staging regs — all instrs full-line
#define LOAD_H(T, H) do {                                                    \
    _Pragma("unroll")                                                        \
    for (int p_ = 0; p_ < 4; p_++) {                                         \
        float4 v_ = *(const float4*)(xA + (size_t)(T) * BK + (H) * 32 + p_ * A_P); \
        stA[p_*4+0]=v_.x; stA[p_*4+1]=v_.y; stA[p_*4+2]=v_.z; stA[p_*4+3]=v_.w; \
    }                                                                        \
    _Pragma("unroll")                                                        \
    for (int q_ = 0; q_ < 8; q_++) {                                         \
        float4 u_ = *(const float4*)(xB                                      \
            + (size_t)((T) * BK + (H) * 32 + 16 * (q_ & 1)) * OUT_D          \
            + (q_ >> 1) * 64);                                               \
        stB[q_*4+0]=u_.x; stB[q_*4+1]=u_.y; stB[q_*4+2]=u_.z; stB[q_*4+3]=u_.w; \
    }                                                                        \
} while (0)

// store staged half H into stage BUF (8B fp16 per lane, conflict-minimal)
#define STS_H(BUF, H) do {                                                   \
    const uint32_t sa_ = ((H) ? saA1 : saA0) + (BUF) * A_STG;                \
    _Pragma("unroll")                                                        \
    for (int p_ = 0; p_ < 4; p_++) {                                         \
        asm volatile("st.shared.v2.b32 [%0], {%1,%2};"                       \
            :: "r"(sa_ + p_ * (32 * A_ROW_B)),                               \
               "r"(packh(stA[p_*4+1], stA[p_*4+0])),                         \
               "r"(packh(stA[p_*4+3], stA[p_*4+2])));                        \
    }                                                                        \
    const uint32_t sb_ = saB + (BUF) * B_STG + (H) * (32 * B_ROW_B);         \
    _Pragma("unroll")                                                        \
    for (int q_ = 0; q_ < 8; q_++) {                                         \
        asm volatile("st.shared.v2.b32 [%0], {%1,%2};"                       \
            :: "r"(sb_ + (q_ & 1) * (16 * B_ROW_B) + (q_ >> 1) * 128),       \
               "r"(packh(stB[q_*4+1], stB[q_*4+0])),                         \
               "r"(packh(stB[q_*4+3], stB[q_*4+2])));                        \
    }                                                                        \
} while (0)

// compute half H (k16 groups 2H, 2H+1) of stage BUF — identical to R13
#define COMPUTE_H(BUF, H) do {                                               \
    _Pragma("unroll")                                                        \
    for (int kk_ = 0; kk_ < 2; kk_++) {                                      \
        const int ks_ = 2 * (H) + kk_;                                       \
        uint32_t a_[4][4];                                                   \
        _Pragma("unroll")                                                    \
        for (int mt_ = 0; mt_ < 4; mt_++)                                    \
            LDSM4(a_[mt_], aBase + (BUF) * A_STG + mt_ * (16 * A_ROW_B) + aoff[ks_]); \
        _Pragma("unroll")                                                    \
        for (int p_ = 0; p_ < 4; p_++) {                                     \
            uint32_t bb_[4];                                                 \
            LDSM4T(bb_, bBase + (BUF) * B_STG + ks_ * (16 * B_ROW_B) + p_ * 32); \
            _Pragma("unroll")                                                \
            for (int mt_ = 0; mt_ < 4; mt_++) {                              \
                MMA16(acc[mt_][2 * p_],     a_[mt_], bb_[0], bb_[1]);        \
                MMA16(acc[mt_][2 * p_ + 1], a_[mt_], bb_[2], bb_[3]);        \
            }                                                                \
        }                                                                    \
    }                                                                        \
} while (0)

    // ---- prologue: tile0 fully staged; tile1 half0 in regs ----
    LOAD_H(0, 0);  STS_H(0, 0);
    LOAD_H(0, 1);  STS_H(0, 1);
    LOAD_H(1, 0);
    __syncthreads();

    // ---- main loop: 3-stage ring, half-tile interleave (R13 schedule) ----
    #pragma unroll 1
    for (int kt = 0; kt < KT; kt++) {
        const int s_cmp = kt % STAGES;
        const int s_nxt = (kt + 1) % STAGES;
        if (kt + 1 < KT) { STS_H(s_nxt, 0); LOAD_H(kt + 1, 1); }
        COMPUTE_H(s_cmp, 0);
        if (kt + 1 < KT) { STS_H(s_nxt, 1); }
        if (kt + 2 < KT) { LOAD_H(kt + 2, 0); }
        COMPUTE_H(s_cmp, 1);
        __syncthreads();
    }

    // ---- epilogue: add bias, store ----
    const float* bp = bias + (size_t)r * OUT_D + n0;
    #pragma unroll
    for (int mt = 0; mt < 4; mt++) {
        #pragma unroll
        for (int nt = 0; nt < 8; nt++) {
            int row0 = wm * 64 + mt * 16 + g;
            int col  = wn * 64 + nt * 8 + tg * 2;
            float b0 = bp[col];
            float b1 = bp[col + 1];
            float2 v0 = make_float2(acc[mt][nt][0] + b0, acc[mt][nt][1] + b1);
            float2 v1 = make_float2(acc[mt][nt][2] + b0, acc[mt][nt][3] + b1);
            size_t o0 = ((size_t)(m0 + row0)     * ROWG + r) * OUT_D + n0 + col;
            size_t o1 = ((size_t)(m0 + row0 + 8) * ROWG + r) * OUT_D + n0 + col;
            *reinterpret_cast<float2*>(out + o0) = v0;
            *reinterpret_cast<float2*>(out + o1) = v1;
        }
    }
}

extern "C" void kernel_launch(void* const* d_in, const int* in_sizes, int n_in,
                              void* d_out, int out_size) {
    const float* x    = (const float*)d_in[0];  // (512, 64, 1024)
    const float* W    = (const float*)d_in[1];  // (64, 1024, 1024)
    const float* bias = (const float*)d_in[2];  // (64, 1024)
    float* out = (float*)d_out;                 // (512, 64, 1024)

    cudaFuncSetAttribute(gmlp_f16cw,
                         cudaFuncAttributeMaxDynamicSharedMemorySize, SMEM_TOTAL);
    dim3 grid(OUT_D / BN, BATCH / BM, ROWG);    // (4, 4, 64)
    gmlp_f16cw<<<grid, 256, SMEM_TOTAL>>>(x, W, bias, out);
}